// round 3
// baseline (speedup 1.0000x reference)
#include <cuda_runtime.h>
#include <math.h>

#define BB 32
#define HH 512
#define WW 512
#define TH 32                    // output rows per block
#define NTHREADS 512
#define NSTRIPES (HH / TH)       // 16
#define NBLK (BB * NSTRIPES)     // 512
#define TILE_ROWS (TH + 4)       // 36 (2-row halo each side)
#define SW 520                   // smem pitch (516 used; cols 0,1,514,515 are halo=0)

// ---- per-block partials (every slot written every call -> no zeroing) ----
__device__ float g_ce[NBLK], g_valid[NBLK], g_focal[NBLK];
__device__ float g_it[NBLK], g_bp[NBLK], g_bt[NBLK];
__device__ unsigned int g_cnt = 0;   // last-block counter (reset by last block)

__device__ __forceinline__ float warp_red_sum(float v) {
    #pragma unroll
    for (int o = 16; o > 0; o >>= 1)
        v += __shfl_down_sync(0xffffffffu, v, o);
    return v;
}

__global__ __launch_bounds__(NTHREADS)
void be_main(const float* __restrict__ pred, const void* __restrict__ target,
             float* __restrict__ out) {
    __shared__ unsigned char st[TILE_ROWS * SW];   // target tile bytes
    __shared__ unsigned char hs[TILE_ROWS * WW];   // horizontal 5-sums (<=5)
    __shared__ float         red[16][6];
    __shared__ int           s_last;

    const int b   = blockIdx.y;
    const int sp  = blockIdx.x;
    const int ry0 = sp * TH;
    const int tid = threadIdx.x;

    // ---- dtype detection over first 16KB (L2-broadcast; both layouts safe).
    // int64 targets (0/1): all hi-words zero. int32: odd words are random 0/1.
    unsigned int v = 0;
    const unsigned int* tw = (const unsigned int*)target;
    #pragma unroll
    for (int i = 0; i < 4; i++)
        v |= tw[2 * (tid + i * NTHREADS) + 1];
    const bool is64 = (__syncthreads_or((int)v) == 0);

    const long long imgBase = (long long)b * (HH * WW);
    const long long* __restrict__ t64 = (const long long*)target;
    const int*       __restrict__ t32 = (const int*)target;

    // ---- zero horizontal halo columns (always out-of-image) ----
    if (tid < TILE_ROWS * 4) {
        int j = tid >> 2, k = tid & 3;
        st[j * SW + (k < 2 ? k : 512 + k)] = 0;
    }

    // ---- load target tile: one coalesced element per thread per row ----
    #pragma unroll 4
    for (int j = 0; j < TILE_ROWS; j++) {
        int gr = ry0 - 2 + j;
        int vv = 0;
        if (gr >= 0 && gr < HH) {
            long long gi = imgBase + (long long)gr * WW + tid;
            vv = is64 ? (int)t64[gi] : t32[gi];
        }
        st[j * SW + 2 + tid] = (unsigned char)vv;
    }
    __syncthreads();

    // ---- horizontal 5-sum (global cols tid-2..tid+2), one col per thread ----
    #pragma unroll 4
    for (int j = 0; j < TILE_ROWS; j++) {
        const unsigned char* r = st + j * SW + tid;
        hs[j * WW + tid] = (unsigned char)((int)r[0] + r[1] + r[2] + r[3] + r[4]);
    }
    __syncthreads();

    // ---- main per-pixel pass: float4 over pred, 4 pixels/iter/thread ----
    float a_ce = 0.f, a_valid = 0.f, a_focal = 0.f;
    float a_it = 0.f, a_bp = 0.f, a_bt = 0.f;

    const float4* __restrict__ p0b =
        (const float4*)(pred + (long long)b * 2 * HH * WW + (long long)ry0 * WW);
    const float4* __restrict__ p1b =
        (const float4*)(pred + (long long)b * 2 * HH * WW + (long long)(HH + ry0) * WW);

    #pragma unroll 4
    for (int k = 0; k < (TH * WW / 4) / NTHREADS; k++) {   // 8 iters
        int g  = tid + k * NTHREADS;
        float4 q0 = p0b[g];
        float4 q1 = p1b[g];
        int rr = g >> 7;                 // (g*4)/512
        int c0 = (g << 2) & (WW - 1);

        #pragma unroll
        for (int u = 0; u < 4; u++) {
            int c = c0 + u;
            float p0 = (&q0.x)[u];
            float p1 = (&q1.x)[u];
            int   t  = (int)st[(rr + 2) * SW + (c + 2)];

            int s = (int)hs[rr * WW + c] + hs[(rr + 1) * WW + c] + hs[(rr + 2) * WW + c]
                  + (int)hs[(rr + 3) * WW + c] + hs[(rr + 4) * WW + c];
            float bnd = (s > 0 && s <= 24) ? 1.f : 0.f;

            // two-class log-softmax via softplus of z = p1 - p0
            float z   = p1 - p0;
            float az  = fabsf(z);
            float e   = __expf(-az);
            float spS = __logf(1.f + e);     // -log p(argmax)
            float spL = az + spS;            // -log p(other)
            float rcp = __fdividef(1.f, 1.f + e);
            float pmax = rcp;
            float pmin = e * rcp;

            int  am1 = (z >= 0.f) ? 1 : 0;
            int  tc  = (t > 1) ? 1 : t;      // take_along_axis clamps OOB index
            float ce = (tc == am1) ? spS : spL;
            float pt = (tc == am1) ? pmax : pmin;
            float prob1 = am1 ? pmax : pmin;

            float valid = (t != 250) ? 1.f : 0.f;
            a_ce    += ce * valid;
            a_valid += valid;
            float om = 1.f - pt;
            a_focal += 0.25f * om * om * ce;

            float tf = (float)t;
            float pb = prob1 * bnd;
            a_bp += pb;
            a_bt += tf * bnd;
            a_it += pb * tf;
        }
    }

    // ---- block reduction (6 values) -> per-block partials ----
    float vals[6] = { a_ce, a_valid, a_focal, a_it, a_bp, a_bt };
    int lane = tid & 31, w = tid >> 5;
    #pragma unroll
    for (int i = 0; i < 6; i++) {
        float r = warp_red_sum(vals[i]);
        if (lane == 0) red[w][i] = r;
    }
    __syncthreads();
    if (tid < 6) {
        float r = 0.f;
        #pragma unroll
        for (int wi = 0; wi < NTHREADS / 32; wi++) r += red[wi][tid];
        int p = b * NSTRIPES + sp;
        if      (tid == 0) g_ce[p]    = r;
        else if (tid == 1) g_valid[p] = r;
        else if (tid == 2) g_focal[p] = r;
        else if (tid == 3) g_it[p]    = r;
        else if (tid == 4) g_bp[p]    = r;
        else               g_bt[p]    = r;
    }
    __syncthreads();

    // ---- last-block final reduction (no second launch) ----
    if (tid == 0) {
        __threadfence();
        unsigned int c = atomicAdd(&g_cnt, 1u);
        s_last = (c == (unsigned int)(NBLK - 1)) ? 1 : 0;
    }
    __syncthreads();
    if (!s_last) return;
    __threadfence();

    // 512 partials; p = b*16 + stripe  ->  16-lane segments per image.
    float it = g_it[tid], bp = g_bp[tid], bt = g_bt[tid];
    float ce = g_ce[tid], va = g_valid[tid], fo = g_focal[tid];

    #pragma unroll
    for (int o = 8; o > 0; o >>= 1) {     // segmented (width 16) reduce
        it += __shfl_down_sync(0xffffffffu, it, o, 16);
        bp += __shfl_down_sync(0xffffffffu, bp, o, 16);
        bt += __shfl_down_sync(0xffffffffu, bt, o, 16);
    }
    float dice = ((tid & 15) == 0) ? 2.f * it / (bp + bt + 1e-8f) : 0.f;

    dice = warp_red_sum(dice);            // two images per warp
    ce = warp_red_sum(ce);
    va = warp_red_sum(va);
    fo = warp_red_sum(fo);
    if (lane == 0) {
        red[w][0] = dice; red[w][1] = ce; red[w][2] = va; red[w][3] = fo;
    }
    __syncthreads();
    if (w == 0 && lane < 16) {
        float d = red[lane][0], cc = red[lane][1], vv = red[lane][2], ff = red[lane][3];
        #pragma unroll
        for (int o = 8; o > 0; o >>= 1) {
            d  += __shfl_down_sync(0xffffu, d, o, 16);
            cc += __shfl_down_sync(0xffffu, cc, o, 16);
            vv += __shfl_down_sync(0xffffu, vv, o, 16);
            ff += __shfl_down_sync(0xffffu, ff, o, 16);
        }
        if (lane == 0) {
            float ce_loss = cc / fmaxf(vv, 1.f);
            float focal   = ff * (1.0f / (float)(BB * HH * WW));
            float bdice   = 1.f - d * (1.0f / (float)BB);
            out[0] = ce_loss + focal + bdice;
            g_cnt = 0u;                    // reset for next graph replay
        }
    }
}

extern "C" void kernel_launch(void* const* d_in, const int* in_sizes, int n_in,
                              void* d_out, int out_size) {
    const void* pred = d_in[0];
    const void* targ = d_in[1];
    if (n_in >= 2 && in_sizes[0] == BB * HH * WW && in_sizes[1] == BB * 2 * HH * WW) {
        pred = d_in[1];
        targ = d_in[0];
    }
    dim3 grid(NSTRIPES, BB);
    be_main<<<grid, NTHREADS>>>((const float*)pred, targ, (float*)d_out);
}

// round 4
// speedup vs baseline: 1.2964x; 1.2964x over previous
#include <cuda_runtime.h>
#include <math.h>

#define BB 32
#define HH 512
#define WW 512
#define TH 16                    // output rows per block
#define NTHREADS 256
#define NSTRIPES (HH / TH)       // 32
#define NBLK (BB * NSTRIPES)     // 1024
#define TILE_ROWS (TH + 4)       // 20
#define SWW 130                  // st row pitch in words (520 bytes; 516 used)
#define WPR 128                  // words per row for hs/cd (512 cols / 4)

// ---- per-block partials (every slot written every call -> no zeroing) ----
__device__ float g_ce[NBLK], g_valid[NBLK], g_focal[NBLK];
__device__ float g_it[NBLK], g_bp[NBLK], g_bt[NBLK];
__device__ unsigned int g_cnt = 0;

__device__ __forceinline__ float warp_red_sum(float v) {
    #pragma unroll
    for (int o = 16; o > 0; o >>= 1)
        v += __shfl_down_sync(0xffffffffu, v, o);
    return v;
}

__global__ __launch_bounds__(NTHREADS, 6)
void be_main(const float* __restrict__ pred, const void* __restrict__ target,
             float* __restrict__ out) {
    __shared__ unsigned int stw[TILE_ROWS * SWW];   // target tile bytes (word view)
    __shared__ unsigned int hsw[TILE_ROWS * WPR];   // horizontal 5-sums, 4 bytes/word
    __shared__ unsigned int cdw[TH * WPR];          // per-pixel codes, 4 bytes/word
    __shared__ float        red[8][6];
    __shared__ int          s_last;

    const int b   = blockIdx.y;
    const int sp  = blockIdx.x;
    const int ry0 = sp * TH;
    const int tid = threadIdx.x;
    unsigned char* st = (unsigned char*)stw;

    // ---- dtype detection (first 16KB, L2-broadcast). int64 targets (0/1):
    // hi-words all zero; int32: odd words are the random 0/1 values.
    unsigned int dv = 0;
    const unsigned int* twd = (const unsigned int*)target;
    #pragma unroll
    for (int i = 0; i < 4; i++)
        dv |= twd[2 * (tid + i * NTHREADS) + 1];
    const bool is64 = (__syncthreads_or((int)dv) == 0);

    const long long imgBase = (long long)b * (HH * WW);
    const long long* __restrict__ t64 = (const long long*)target;
    const int*       __restrict__ t32 = (const int*)target;

    // ---- zero horizontal halo bytes (cols 0,1,514,515 of each row) ----
    if (tid < TILE_ROWS * 4) {
        int j = tid >> 2, k = tid & 3;
        st[j * (SWW * 4) + (k < 2 ? k : 512 + k)] = 0;
    }

    // ---- load target tile: 2 coalesced elements per thread per row ----
    #pragma unroll 2
    for (int j = 0; j < TILE_ROWS; j++) {
        int gr = ry0 - 2 + j;
        int v0 = 0, v1 = 0;
        if (gr >= 0 && gr < HH) {
            long long gi = imgBase + (long long)gr * WW;
            if (is64) { v0 = (int)t64[gi + tid]; v1 = (int)t64[gi + tid + NTHREADS]; }
            else      { v0 = t32[gi + tid];      v1 = t32[gi + tid + NTHREADS]; }
        }
        st[j * (SWW * 4) + 2 + tid] = (unsigned char)v0;
        st[j * (SWW * 4) + 2 + tid + NTHREADS] = (unsigned char)v1;
    }
    __syncthreads();

    // ---- horizontal 5-sum, word-SIMD: 4 columns at a time ----
    #pragma unroll 2
    for (int idx = tid; idx < TILE_ROWS * WPR; idx += NTHREADS) {
        int j = idx >> 7, w = idx & (WPR - 1);
        unsigned int A = stw[j * SWW + w];
        unsigned int B = stw[j * SWW + w + 1];
        // byte lane u sums st idx 4w+u .. 4w+u+4 (global cols 4w+u-2..+2)
        unsigned int s = A
                       + __byte_perm(A, B, 0x4321)
                       + __byte_perm(A, B, 0x5432)
                       + __byte_perm(A, B, 0x6543)
                       + B;
        hsw[idx] = s;
    }
    __syncthreads();

    // ---- vertical 5-sum + boundary + code pack ----
    #pragma unroll 2
    for (int idx = tid; idx < TH * WPR; idx += NTHREADS) {
        int rr = idx >> 7, w = idx & (WPR - 1);
        unsigned int s = hsw[rr * WPR + w] + hsw[(rr + 1) * WPR + w]
                       + hsw[(rr + 2) * WPR + w] + hsw[(rr + 3) * WPR + w]
                       + hsw[(rr + 4) * WPR + w];
        unsigned int bnd = __vcmpgtu4(s, 0u) & ~__vcmpgtu4(s, 0x18181818u); // 1<=s<=24
        unsigned int A = stw[(rr + 2) * SWW + w];
        unsigned int B = stw[(rr + 2) * SWW + w + 1];
        unsigned int t = __byte_perm(A, B, 0x5432);        // bytes for cols 4w..4w+3
        unsigned int gt1   = __vcmpgtu4(t, 0x01010101u);
        unsigned int ne250 = ~__vcmpeq4(t, 0xFAFAFAFAu);
        unsigned int code  = ((t | gt1) & 0x01010101u)     // bit0: clamped class
                           | (bnd & 0x02020202u)           // bit1: boundary
                           | (ne250 & 0x04040404u);        // bit2: valid
        cdw[idx] = code;
    }
    __syncthreads();

    // ---- main pass: 2 LDG.128 + 1 LDS.32 per 4 pixels ----
    float a_ce = 0.f, a_valid = 0.f, a_focal = 0.f;
    float a_it = 0.f, a_bp = 0.f, a_bt = 0.f;

    const float4* __restrict__ p0b =
        (const float4*)(pred + (long long)b * 2 * HH * WW + (long long)ry0 * WW);
    const float4* __restrict__ p1b =
        (const float4*)(pred + (long long)b * 2 * HH * WW + (long long)(HH + ry0) * WW);

    #pragma unroll 2
    for (int k = 0; k < (TH * WW / 4) / NTHREADS; k++) {   // 8 iters
        int g = tid + k * NTHREADS;
        float4 q0 = p0b[g];
        float4 q1 = p1b[g];
        unsigned int cw = cdw[g];

        #pragma unroll
        for (int u = 0; u < 4; u++) {
            unsigned int c3 = (cw >> (8 * u)) & 7u;
            float p0 = (&q0.x)[u];
            float p1 = (&q1.x)[u];

            float z   = p1 - p0;
            float az  = fabsf(z);
            float e   = __expf(-az);
            float spS = __logf(1.f + e);       // -log p(argmax)
            float spL = az + spS;              // -log p(other)
            float rcp = __fdividef(1.f, 1.f + e);
            float pmax = rcp;
            float pmin = e * rcp;

            int  am1   = (z >= 0.f) ? 1 : 0;
            int  tc    = (int)(c3 & 1u);
            float bnd  = (c3 & 2u) ? 1.f : 0.f;
            float valid = (c3 & 4u) ? 1.f : 0.f;

            float ce    = (tc == am1) ? spS : spL;
            float pt    = (tc == am1) ? pmax : pmin;
            float prob1 = am1 ? pmax : pmin;

            a_ce    += ce * valid;
            a_valid += valid;
            float om = 1.f - pt;
            a_focal += 0.25f * om * om * ce;

            float tf = (c3 & 4u) ? (float)tc : 250.f;   // real label value
            float pb = prob1 * bnd;
            a_bp += pb;
            a_bt += tf * bnd;
            a_it += pb * tf;
        }
    }

    // ---- block reduction -> per-block partials ----
    float vals[6] = { a_ce, a_valid, a_focal, a_it, a_bp, a_bt };
    int lane = tid & 31, w = tid >> 5;
    #pragma unroll
    for (int i = 0; i < 6; i++) {
        float r = warp_red_sum(vals[i]);
        if (lane == 0) red[w][i] = r;
    }
    __syncthreads();
    if (tid < 6) {
        float r = 0.f;
        #pragma unroll
        for (int wi = 0; wi < NTHREADS / 32; wi++) r += red[wi][tid];
        int p = b * NSTRIPES + sp;
        if      (tid == 0) g_ce[p]    = r;
        else if (tid == 1) g_valid[p] = r;
        else if (tid == 2) g_focal[p] = r;
        else if (tid == 3) g_it[p]    = r;
        else if (tid == 4) g_bp[p]    = r;
        else               g_bt[p]    = r;
    }
    __syncthreads();

    // ---- last-block final reduction (single launch total) ----
    if (tid == 0) {
        __threadfence();
        unsigned int c = atomicAdd(&g_cnt, 1u);
        s_last = (c == (unsigned int)(NBLK - 1)) ? 1 : 0;
    }
    __syncthreads();
    if (!s_last) return;
    __threadfence();

    // 1024 partials, image b occupies [b*32, b*32+32). 8 warps x 4 images each.
    float dsum = 0.f, csum = 0.f, vsum = 0.f, fsum = 0.f;
    #pragma unroll
    for (int i = 0; i < 4; i++) {
        int img = w * 4 + i;
        int p = img * NSTRIPES + lane;
        float it = g_it[p], bp = g_bp[p], bt = g_bt[p];
        float ce = g_ce[p], va = g_valid[p], fo = g_focal[p];
        it = warp_red_sum(it); bp = warp_red_sum(bp); bt = warp_red_sum(bt);
        ce = warp_red_sum(ce); va = warp_red_sum(va); fo = warp_red_sum(fo);
        if (lane == 0) {
            dsum += 2.f * it / (bp + bt + 1e-8f);
            csum += ce; vsum += va; fsum += fo;
        }
    }
    if (lane == 0) {
        red[w][0] = dsum; red[w][1] = csum; red[w][2] = vsum; red[w][3] = fsum;
    }
    __syncthreads();
    if (tid == 0) {
        float d = 0.f, cc = 0.f, vv = 0.f, ff = 0.f;
        #pragma unroll
        for (int wi = 0; wi < 8; wi++) {
            d += red[wi][0]; cc += red[wi][1]; vv += red[wi][2]; ff += red[wi][3];
        }
        float ce_loss = cc / fmaxf(vv, 1.f);
        float focal   = ff * (1.0f / (float)(BB * HH * WW));
        float bdice   = 1.f - d * (1.0f / (float)BB);
        out[0] = ce_loss + focal + bdice;
        g_cnt = 0u;                        // reset for next graph replay
    }
}

extern "C" void kernel_launch(void* const* d_in, const int* in_sizes, int n_in,
                              void* d_out, int out_size) {
    const void* pred = d_in[0];
    const void* targ = d_in[1];
    if (n_in >= 2 && in_sizes[0] == BB * HH * WW && in_sizes[1] == BB * 2 * HH * WW) {
        pred = d_in[1];
        targ = d_in[0];
    }
    dim3 grid(NSTRIPES, BB);
    be_main<<<grid, NTHREADS>>>((const float*)pred, targ, (float*)d_out);
}